// round 1
// baseline (speedup 1.0000x reference)
#include <cuda_runtime.h>

#define N_AG  1024
#define HID   128
#define SGRID 32
#define CELLS (SGRID * SGRID)   // 1024
#define KDIM  2048              // HID * 16 pooled blocks
#define OUTD  128
#define SK    8                 // split-K factor
#define KS    (KDIM / SK)       // 256
#define BM    64
#define BK    16

// Scratch (no allocs allowed): 4MB + 8MB + 4MB
__device__ int   g_winner[N_AG * CELLS];
__device__ float g_flat[N_AG * KDIM];
__device__ float g_part[SK * N_AG * OUTD];

// ---------------------------------------------------------------------------
// Kernel 0: reset winner grid to -1 (must happen every launch; graph-safe)
// ---------------------------------------------------------------------------
__global__ void init_winner_kernel() {
    int idx = blockIdx.x * blockDim.x + threadIdx.x;   // 1024*256 threads, int4 each
    ((int4*)g_winner)[idx] = make_int4(-1, -1, -1, -1);
}

// ---------------------------------------------------------------------------
// Kernel 1: for each ego i, atomicMax neighbor index j into its cell.
// Reproduces XLA scatter-SET duplicate resolution (last update = max j wins).
// ---------------------------------------------------------------------------
__global__ void scatter_kernel(const float* __restrict__ obs2) {
    __shared__ float2 s_obs[N_AG];
    const int i = blockIdx.x;
    for (int j = threadIdx.x; j < N_AG; j += blockDim.x)
        s_obs[j] = ((const float2*)obs2)[j];
    __syncthreads();

    const float xi = s_obs[i].x;
    const float yi = s_obs[i].y;
    if (xi != xi) return;   // ego NaN -> no valid pairs (uniform across block)

    int* wrow = g_winner + i * CELLS;
    for (int j = threadIdx.x; j < N_AG; j += blockDim.x) {
        if (j == i) continue;
        float xj = s_obs[j].x, yj = s_obs[j].y;
        if (xj != xj) continue;                        // neighbor NaN
        // oij = rel / (2.0/8) + 32/2  (exact: *4 is a power-of-two scale)
        float ox = (xj - xi) * 4.0f + 16.0f;
        float oy = (yj - yi) * 4.0f + 16.0f;
        if (ox >= 0.0f && ox < 32.0f && oy >= 0.0f && oy < 32.0f) {
            int cell = ((int)ox) * SGRID + (int)oy;    // truncation == floor (>=0)
            atomicMax(&wrow[cell], j);
        }
    }
}

// ---------------------------------------------------------------------------
// Kernel 2: per-ego gather of winning hidden states, 8x8 sum-pool into 4x4
// blocks, write channel-first flattened features flat[i, h*16 + gi*4 + gj].
// 128 threads = one thread per hidden channel.
// ---------------------------------------------------------------------------
__global__ void pool_kernel(const float* __restrict__ hidden) {
    __shared__ float pooled[16][HID + 1];  // +1 pad: conflict-free transpose read
    __shared__ int   s_ent[CELLS];
    __shared__ int   s_cnt;

    const int i = blockIdx.x;
    const int t = threadIdx.x;             // 0..127 (channel)

    if (t == 0) s_cnt = 0;
    for (int f = t; f < 16 * (HID + 1); f += 128)
        (&pooled[0][0])[f] = 0.0f;
    __syncthreads();

    // compact occupied cells
    const int* wrow = g_winner + i * CELLS;
    for (int c = t; c < CELLS; c += 128) {
        int w = wrow[c];
        if (w >= 0) {
            int p = atomicAdd(&s_cnt, 1);
            s_ent[p] = (w << 10) | c;      // j in [0,1024), c in [0,1024)
        }
    }
    __syncthreads();

    const int cnt = s_cnt;
    for (int e = 0; e < cnt; e++) {
        int ent  = s_ent[e];
        int c    = ent & 1023;
        int j    = ent >> 10;
        int blk  = ((c >> 8) << 2) | ((c & 31) >> 3);  // gi*4 + gj
        pooled[blk][t] += hidden[j * HID + t];
    }
    __syncthreads();

    float* frow = g_flat + i * KDIM;
    for (int f = t; f < KDIM; f += 128)
        frow[f] = pooled[f & 15][f >> 4];  // flat[h*16+blk] = pooled[blk][h]
}

// ---------------------------------------------------------------------------
// Kernel 3: split-K SGEMM partials: part[ks][m][n] = sum_{k in slice} flat*W
//   flat [1024 x 2048], W [128 x 2048] (row-major, out = flat @ W^T)
//   grid (16 M-tiles, 8 K-splits), 256 thr, 64x128 tile, 4x8 microtile
// ---------------------------------------------------------------------------
__global__ void gemm_kernel(const float* __restrict__ W) {
    __shared__ float As[BK][BM];     // A transposed: As[k][m]
    __shared__ float Bs[BK][OUTD];   // Bs[k][n]

    const int mtile = blockIdx.x;
    const int ks    = blockIdx.y;
    const int t     = threadIdx.x;       // 256
    const int ty    = t >> 4;            // 0..15 -> 4 rows each
    const int tx    = t & 15;            // 0..15 -> 8 cols each
    const int row0  = mtile * BM;
    const int k0    = ks * KS;

    float acc[4][8];
#pragma unroll
    for (int r = 0; r < 4; r++)
#pragma unroll
        for (int c = 0; c < 8; c++) acc[r][c] = 0.0f;

    for (int kk = 0; kk < KS; kk += BK) {
        {   // A tile: 64x16 = 1024 floats, one float4 per thread
            int m = t >> 2, kq = t & 3;
            float4 v = *(const float4*)(g_flat + (row0 + m) * KDIM + k0 + kk + kq * 4);
            As[kq * 4 + 0][m] = v.x;
            As[kq * 4 + 1][m] = v.y;
            As[kq * 4 + 2][m] = v.z;
            As[kq * 4 + 3][m] = v.w;
        }
#pragma unroll
        for (int p = 0; p < 2; p++) {  // B tile: 16x128 = 2048 floats
            int idx = t + p * 256;
            int n = idx >> 2, kq = idx & 3;
            float4 v = *(const float4*)(W + n * KDIM + k0 + kk + kq * 4);
            Bs[kq * 4 + 0][n] = v.x;
            Bs[kq * 4 + 1][n] = v.y;
            Bs[kq * 4 + 2][n] = v.z;
            Bs[kq * 4 + 3][n] = v.w;
        }
        __syncthreads();

#pragma unroll
        for (int k = 0; k < BK; k++) {
            float a[4], bb[8];
#pragma unroll
            for (int r = 0; r < 4; r++) a[r] = As[k][ty * 4 + r];
#pragma unroll
            for (int c = 0; c < 8; c++) bb[c] = Bs[k][tx * 8 + c];
#pragma unroll
            for (int r = 0; r < 4; r++)
#pragma unroll
                for (int c = 0; c < 8; c++) acc[r][c] += a[r] * bb[c];
        }
        __syncthreads();
    }

    float* pbase = g_part + ks * (N_AG * OUTD);
#pragma unroll
    for (int r = 0; r < 4; r++) {
        int m = row0 + ty * 4 + r;
        *(float4*)(pbase + m * OUTD + tx * 8)     =
            make_float4(acc[r][0], acc[r][1], acc[r][2], acc[r][3]);
        *(float4*)(pbase + m * OUTD + tx * 8 + 4) =
            make_float4(acc[r][4], acc[r][5], acc[r][6], acc[r][7]);
    }
}

// ---------------------------------------------------------------------------
// Kernel 4: reduce split-K partials + bias + ReLU
// ---------------------------------------------------------------------------
__global__ void reduce_relu_kernel(const float* __restrict__ b, float* __restrict__ out) {
    int idx = blockIdx.x * blockDim.x + threadIdx.x;  // 32768 float4s
    float4 s = make_float4(0.f, 0.f, 0.f, 0.f);
#pragma unroll
    for (int p = 0; p < SK; p++) {
        float4 v = ((const float4*)(g_part + p * N_AG * OUTD))[idx];
        s.x += v.x; s.y += v.y; s.z += v.z; s.w += v.w;
    }
    float4 bv = ((const float4*)b)[idx & (OUTD / 4 - 1)];
    s.x = fmaxf(s.x + bv.x, 0.f);
    s.y = fmaxf(s.y + bv.y, 0.f);
    s.z = fmaxf(s.z + bv.z, 0.f);
    s.w = fmaxf(s.w + bv.w, 0.f);
    ((float4*)out)[idx] = s;
}

// ---------------------------------------------------------------------------
extern "C" void kernel_launch(void* const* d_in, const int* in_sizes, int n_in,
                              void* d_out, int out_size) {
    const float* hidden = (const float*)d_in[0];
    // d_in[1] = obs1 (unused by reference)
    const float* obs2   = (const float*)d_in[2];
    const float* W      = (const float*)d_in[3];
    const float* b      = (const float*)d_in[4];
    float*       out    = (float*)d_out;

    init_winner_kernel<<<1024, 256>>>();
    scatter_kernel<<<N_AG, 256>>>(obs2);
    pool_kernel<<<N_AG, 128>>>(hidden);
    dim3 ggrid(N_AG / BM, SK);   // (16, 8)
    gemm_kernel<<<ggrid, 256>>>(W);
    reduce_relu_kernel<<<(N_AG * OUTD / 4) / 256, 256>>>(b, out);
}

// round 2
// speedup vs baseline: 1.3257x; 1.3257x over previous
#include <cuda_runtime.h>

#define N_AG  1024
#define HID   128
#define SGRID 32
#define CELLS 1024
#define KDIM  2048            // 16 blocks * 128 hid
#define OUTD  128

// Scratch (no allocs allowed)
__device__ float g_wperm[KDIM * HID];      // 1 MB : Wperm[(blk*128+n)][h]
__device__ float g_P[N_AG * KDIM];         // 8 MB : P[j][blk*128+n]
__device__ int   g_ent[N_AG * CELLS];      // 4 MB : per-ego row offsets into P
__device__ int   g_cnt[N_AG];

// ---------------------------------------------------------------------------
// Kernel 1: permute W[n][h*16+blk] -> Wperm[blk*128+n][h]
// ---------------------------------------------------------------------------
__global__ void perm_kernel(const float* __restrict__ W) {
    int idx = blockIdx.x * blockDim.x + threadIdx.x;   // 262144 elements
    int n = idx >> 11;            // 0..127
    int k = idx & 2047;           // h*16+blk
    int h = k >> 4, blk = k & 15;
    g_wperm[((blk << 7) | n) * HID + h] = W[idx];
}

// ---------------------------------------------------------------------------
// Kernel 2: per-ego winner grid in SMEM (set-semantics: max j wins, matching
// XLA scatter update order), compact occupied cells to row offsets into P.
// ---------------------------------------------------------------------------
__global__ void scatter_kernel(const float* __restrict__ obs2) {
    __shared__ float2 s_obs[N_AG];
    __shared__ int    w[CELLS];
    __shared__ int    cnt;
    const int i = blockIdx.x;
    const int t = threadIdx.x;   // 256

    for (int j = t; j < N_AG; j += 256) {
        s_obs[j] = ((const float2*)obs2)[j];
    }
    for (int c = t; c < CELLS; c += 256) w[c] = -1;
    if (t == 0) cnt = 0;
    __syncthreads();

    const float xi = s_obs[i].x;
    const float yi = s_obs[i].y;
    if (xi != xi) {              // ego NaN -> zero valid neighbors
        if (t == 0) g_cnt[i] = 0;
        return;
    }

    for (int j = t; j < N_AG; j += 256) {
        if (j == i) continue;
        float xj = s_obs[j].x, yj = s_obs[j].y;
        if (xj != xj) continue;
        float ox = (xj - xi) * 4.0f + 16.0f;   // exact power-of-two scale
        float oy = (yj - yi) * 4.0f + 16.0f;
        if (ox >= 0.0f && ox < 32.0f && oy >= 0.0f && oy < 32.0f) {
            int cell = ((int)ox) * SGRID + (int)oy;
            atomicMax(&w[cell], j);
        }
    }
    __syncthreads();

    int* ent = g_ent + i * CELLS;
    for (int c = t; c < CELLS; c += 256) {
        int j = w[c];
        if (j >= 0) {
            int blk = ((c >> 8) << 2) | ((c & 31) >> 3);  // gi*4+gj
            int p = atomicAdd(&cnt, 1);
            ent[p] = j * KDIM + (blk << 7);               // row offset into P
        }
    }
    __syncthreads();
    if (t == 0) g_cnt[i] = cnt;
}

// ---------------------------------------------------------------------------
// Kernel 3: P = hidden @ Wperm^T.  M=1024, N=2048, K=128.
// 128x128 tiles, 8x8 microtile, double-buffered smem, register prefetch.
// grid (8, 16) = 128 CTAs, 256 threads.
// ---------------------------------------------------------------------------
__global__ void __launch_bounds__(256, 1) gemm_kernel(const float* __restrict__ A) {
    __shared__ float As[2][16][128];
    __shared__ float Bs[2][16][128];

    const int t  = threadIdx.x;
    const int m0 = blockIdx.x << 7;
    const int n0 = blockIdx.y << 7;
    const int lm = t >> 1;           // tile row (0..127)
    const int lq = t & 1;            // half-row (8 floats)
    const int ty = t >> 4;           // 0..15 -> m micro
    const int tx = t & 15;           // 0..15 -> n micro

    const float* Ab = A       + (m0 + lm) * HID + lq * 8;
    const float* Bb = g_wperm + (n0 + lm) * HID + lq * 8;

    float acc[8][8];
#pragma unroll
    for (int r = 0; r < 8; r++)
#pragma unroll
        for (int c = 0; c < 8; c++) acc[r][c] = 0.0f;

    float4 a0 = *(const float4*)(Ab);
    float4 a1 = *(const float4*)(Ab + 4);
    float4 b0 = *(const float4*)(Bb);
    float4 b1 = *(const float4*)(Bb + 4);
#pragma unroll
    for (int s = 0; s < 4; s++) {
        As[0][lq * 8 + s][lm]     = ((const float*)&a0)[s];
        As[0][lq * 8 + 4 + s][lm] = ((const float*)&a1)[s];
        Bs[0][lq * 8 + s][lm]     = ((const float*)&b0)[s];
        Bs[0][lq * 8 + 4 + s][lm] = ((const float*)&b1)[s];
    }
    __syncthreads();

#pragma unroll
    for (int kk = 0; kk < 8; kk++) {
        const int cur = kk & 1;
        if (kk < 7) {
            a0 = *(const float4*)(Ab + (kk + 1) * 16);
            a1 = *(const float4*)(Ab + (kk + 1) * 16 + 4);
            b0 = *(const float4*)(Bb + (kk + 1) * 16);
            b1 = *(const float4*)(Bb + (kk + 1) * 16 + 4);
        }
#pragma unroll
        for (int k = 0; k < 16; k++) {
            float a[8], b[8];
            *(float4*)&a[0] = *(const float4*)&As[cur][k][ty * 8];
            *(float4*)&a[4] = *(const float4*)&As[cur][k][ty * 8 + 4];
            *(float4*)&b[0] = *(const float4*)&Bs[cur][k][tx * 8];
            *(float4*)&b[4] = *(const float4*)&Bs[cur][k][tx * 8 + 4];
#pragma unroll
            for (int r = 0; r < 8; r++)
#pragma unroll
                for (int c = 0; c < 8; c++) acc[r][c] += a[r] * b[c];
        }
        if (kk < 7) {
            const int nxt = cur ^ 1;
#pragma unroll
            for (int s = 0; s < 4; s++) {
                As[nxt][lq * 8 + s][lm]     = ((const float*)&a0)[s];
                As[nxt][lq * 8 + 4 + s][lm] = ((const float*)&a1)[s];
                Bs[nxt][lq * 8 + s][lm]     = ((const float*)&b0)[s];
                Bs[nxt][lq * 8 + 4 + s][lm] = ((const float*)&b1)[s];
            }
            __syncthreads();
        }
    }

    float* Pr = g_P + (m0 + ty * 8) * KDIM + n0 + tx * 8;
#pragma unroll
    for (int r = 0; r < 8; r++) {
        *(float4*)(Pr + r * KDIM)     = make_float4(acc[r][0], acc[r][1], acc[r][2], acc[r][3]);
        *(float4*)(Pr + r * KDIM + 4) = make_float4(acc[r][4], acc[r][5], acc[r][6], acc[r][7]);
    }
}

// ---------------------------------------------------------------------------
// Kernel 4: out[i][n] = relu(b[n] + sum_e P[ent_e + n])
// ---------------------------------------------------------------------------
__global__ void out_kernel(const float* __restrict__ b, float* __restrict__ out) {
    __shared__ int se[CELLS];
    const int i = blockIdx.x;
    const int t = threadIdx.x;   // 128 = output channel

    const int cnt = g_cnt[i];
    const int* ent = g_ent + i * CELLS;
    for (int e = t; e < cnt; e += 128) se[e] = ent[e];
    __syncthreads();

    float acc = b[t];
    for (int e = 0; e < cnt; e++)
        acc += g_P[se[e] + t];
    out[i * OUTD + t] = fmaxf(acc, 0.0f);
}

// ---------------------------------------------------------------------------
extern "C" void kernel_launch(void* const* d_in, const int* in_sizes, int n_in,
                              void* d_out, int out_size) {
    const float* hidden = (const float*)d_in[0];
    const float* obs2   = (const float*)d_in[2];
    const float* W      = (const float*)d_in[3];
    const float* b      = (const float*)d_in[4];
    float*       out    = (float*)d_out;

    perm_kernel<<<KDIM * HID / 256, 256>>>(W);
    scatter_kernel<<<N_AG, 256>>>(obs2);
    dim3 ggrid(N_AG / 128, KDIM / 128);   // (8, 16)
    gemm_kernel<<<ggrid, 256>>>(hidden);
    out_kernel<<<N_AG, 128>>>(b, out);
}

// round 4
// speedup vs baseline: 1.7758x; 1.3396x over previous
#include <cuda_runtime.h>
#include <cuda_bf16.h>
#include <cstdint>

#define N_AG  1024
#define HID   128
#define KDIM  2048
#define OUTD  128
#define CELLS 1024

// ---- scratch (device globals; no allocs allowed) ----
__device__ __nv_bfloat16 g_Ah[N_AG * HID];     // hidden hi
__device__ __nv_bfloat16 g_Al[N_AG * HID];     // hidden lo
__device__ __nv_bfloat16 g_Bh[KDIM * HID];     // Wperm hi
__device__ __nv_bfloat16 g_Bl[KDIM * HID];     // Wperm lo
__device__ float g_P[N_AG * KDIM];             // 8 MB projections
__device__ int   g_ent[N_AG * CELLS];
__device__ int   g_cnt[N_AG];

__device__ __forceinline__ uint32_t smem_u32(const void* p) {
    uint32_t a;
    asm("{ .reg .u64 t; cvta.to.shared.u64 t, %1; cvt.u32.u64 %0, t; }" : "=r"(a) : "l"(p));
    return a;
}
__device__ __forceinline__ void ldsm_x4(uint32_t& r0, uint32_t& r1, uint32_t& r2, uint32_t& r3,
                                        uint32_t addr) {
    asm volatile("ldmatrix.sync.aligned.m8n8.x4.shared.b16 {%0,%1,%2,%3}, [%4];"
                 : "=r"(r0), "=r"(r1), "=r"(r2), "=r"(r3) : "r"(addr));
}
__device__ __forceinline__ void mma16816(float* c, const uint32_t* a, const uint32_t* b) {
    asm volatile("mma.sync.aligned.m16n8k16.row.col.f32.bf16.bf16.f32 "
                 "{%0,%1,%2,%3}, {%4,%5,%6,%7}, {%8,%9}, {%0,%1,%2,%3};"
                 : "+f"(c[0]), "+f"(c[1]), "+f"(c[2]), "+f"(c[3])
                 : "r"(a[0]), "r"(a[1]), "r"(a[2]), "r"(a[3]), "r"(b[0]), "r"(b[1]));
}

// ============================ prep kernels ===================================
__global__ void convW_kernel(const float* __restrict__ W) {
    int idx = blockIdx.x * 256 + threadIdx.x;       // 262144
    float v = W[idx];
    int n = idx >> 11, k = idx & 2047;
    int h = k >> 4, blk = k & 15;
    int row = (blk << 7) | n;                       // Wperm row
    __nv_bfloat16 hi = __float2bfloat16(v);
    g_Bh[row * HID + h] = hi;
    g_Bl[row * HID + h] = __float2bfloat16(v - __bfloat162float(hi));
}
__global__ void convH_kernel(const float* __restrict__ Hs) {
    int idx = blockIdx.x * 256 + threadIdx.x;       // 131072
    float v = Hs[idx];
    __nv_bfloat16 hi = __float2bfloat16(v);
    g_Ah[idx] = hi;
    g_Al[idx] = __float2bfloat16(v - __bfloat162float(hi));
}

// ============================ scatter (8 egos/CTA) ===========================
__global__ void scatter_kernel(const float* __restrict__ obs2) {
    __shared__ float2 s_obs[N_AG];
    __shared__ int    w[8][CELLS];
    __shared__ int    cnt[8];
    const int t  = threadIdx.x;   // 256
    const int i0 = blockIdx.x * 8;

    for (int j = t; j < N_AG; j += 256) s_obs[j] = ((const float2*)obs2)[j];
    for (int c = t; c < 8 * CELLS; c += 256) (&w[0][0])[c] = -1;
    if (t < 8) cnt[t] = 0;
    __syncthreads();

#pragma unroll
    for (int e = 0; e < 8; e++) {
        const int i = i0 + e;
        const float xi = s_obs[i].x, yi = s_obs[i].y;
        if (xi != xi) continue;                      // ego NaN
        for (int j = t; j < N_AG; j += 256) {
            if (j == i) continue;
            float xj = s_obs[j].x, yj = s_obs[j].y;
            if (xj != xj) continue;
            float ox = (xj - xi) * 4.0f + 16.0f;     // exact pow2 scale
            float oy = (yj - yi) * 4.0f + 16.0f;
            if (ox >= 0.0f && ox < 32.0f && oy >= 0.0f && oy < 32.0f)
                atomicMax(&w[e][((int)ox) * 32 + (int)oy], j);   // set-sem: max j
        }
    }
    __syncthreads();

#pragma unroll
    for (int e = 0; e < 8; e++) {
        const int i = i0 + e;
        int* ent = g_ent + (i << 10);
        for (int c = t; c < CELLS; c += 256) {
            int j = w[e][c];
            if (j >= 0) {
                int blk = ((c >> 8) << 2) | ((c & 31) >> 3);
                int p = atomicAdd(&cnt[e], 1);
                ent[p] = (j << 11) | (blk << 7);     // offset into P
            }
        }
    }
    __syncthreads();
    if (t < 8) g_cnt[i0 + t] = cnt[t];
}

// ============================ mma.sync GEMM ==================================
// P = hidden(1024x128) @ Wperm^T(2048x128). grid(8,16), 256 thr, 128x128 tile.
// 3 bf16 passes (Ah*Bh + Ah*Bl + Al*Bh) in fp32 acc. Whole K staged in smem.
#define LDS   136                          // padded row stride (bf16)
#define TILE  (128 * LDS)                  // elements per tile
#define SMEM_DYN (4 * TILE * 2)            // 4 tiles, bytes (139264)

__device__ __forceinline__ void load_tile(__nv_bfloat16* dst, const __nv_bfloat16* src,
                                          int row0) {
    const int t = threadIdx.x;             // 256
#pragma unroll
    for (int q = t; q < 2048; q += 256) {  // 16B chunks
        int r = q >> 4, c = q & 15;
        uint4 v = *(const uint4*)(src + (row0 + r) * HID + c * 8);
        *(uint4*)(dst + r * LDS + c * 8) = v;
    }
}

__global__ void __launch_bounds__(256, 1) gemm_mma_kernel() {
    extern __shared__ __nv_bfloat16 sm[];
    __nv_bfloat16* sAh = sm;
    __nv_bfloat16* sAl = sm + TILE;
    __nv_bfloat16* sBh = sm + 2 * TILE;
    __nv_bfloat16* sBl = sm + 3 * TILE;

    const int t  = threadIdx.x;
    const int w  = t >> 5;
    const int l  = t & 31;
    const int m0 = blockIdx.x << 7;
    const int n0 = blockIdx.y << 7;
    const int wm = (w >> 2) * 64;          // warp m offset in tile
    const int wn = (w & 3) * 32;           // warp n offset in tile

    load_tile(sAh, g_Ah, m0);
    load_tile(sAl, g_Al, m0);
    load_tile(sBh, g_Bh, n0);
    load_tile(sBl, g_Bl, n0);
    __syncthreads();

    float acc[4][4][4];
#pragma unroll
    for (int mi = 0; mi < 4; mi++)
#pragma unroll
        for (int ni = 0; ni < 4; ni++)
#pragma unroll
            for (int q = 0; q < 4; q++) acc[mi][ni][q] = 0.0f;

    // per-lane ldmatrix address offsets (in elements)
    const int aRow = wm + (l & 15);
    const int aCol = (l >> 4) * 8;
    const int bRow = wn + ((l >> 4) * 8) + (l & 7);
    const int bCol = ((l >> 3) & 1) * 8;

    const __nv_bfloat16* Amat[3] = { sAh, sAh, sAl };
    const __nv_bfloat16* Bmat[3] = { sBh, sBl, sBh };

#pragma unroll
    for (int pass = 0; pass < 3; pass++) {
        const uint32_t aBase = smem_u32(Amat[pass] + aRow * LDS + aCol);
        const uint32_t bBase = smem_u32(Bmat[pass] + bRow * LDS + bCol);
#pragma unroll
        for (int kk = 0; kk < 8; kk++) {
            uint32_t aF[4][4], bF[4][2];
#pragma unroll
            for (int mi = 0; mi < 4; mi++)
                ldsm_x4(aF[mi][0], aF[mi][1], aF[mi][2], aF[mi][3],
                        aBase + (mi * 16 * LDS + kk * 16) * 2);
#pragma unroll
            for (int bi = 0; bi < 2; bi++)
                ldsm_x4(bF[2 * bi][0], bF[2 * bi][1], bF[2 * bi + 1][0], bF[2 * bi + 1][1],
                        bBase + (bi * 16 * LDS + kk * 16) * 2);
#pragma unroll
            for (int mi = 0; mi < 4; mi++)
#pragma unroll
                for (int ni = 0; ni < 4; ni++)
                    mma16816(acc[mi][ni], aF[mi], bF[ni]);
        }
    }

    // epilogue: c0,c1 -> (row g, col 2tig); c2,c3 -> (row g+8)
    const int g2 = l >> 2, tig = l & 3;
#pragma unroll
    for (int mi = 0; mi < 4; mi++) {
        const int row = m0 + wm + mi * 16 + g2;
#pragma unroll
        for (int ni = 0; ni < 4; ni++) {
            const int col = n0 + wn + ni * 8 + tig * 2;
            *(float2*)(g_P + row * KDIM + col)       = make_float2(acc[mi][ni][0], acc[mi][ni][1]);
            *(float2*)(g_P + (row + 8) * KDIM + col) = make_float2(acc[mi][ni][2], acc[mi][ni][3]);
        }
    }
}

// ============================ output gather =================================
__global__ void out_kernel(const float* __restrict__ b, float* __restrict__ out) {
    __shared__ int    se[CELLS];
    __shared__ float4 sp[8][32];
    const int i = blockIdx.x;
    const int t = threadIdx.x;     // 256
    const int g = t >> 5, l = t & 31;

    const int cnt = g_cnt[i];
    const int* ent = g_ent + (i << 10);
    for (int e = t; e < cnt; e += 256) se[e] = ent[e];
    __syncthreads();

    float4 acc = make_float4(0.f, 0.f, 0.f, 0.f);
    for (int e = g; e < cnt; e += 8) {
        float4 v = *(const float4*)(g_P + se[e] + l * 4);
        acc.x += v.x; acc.y += v.y; acc.z += v.z; acc.w += v.w;
    }
    sp[g][l] = acc;
    __syncthreads();

    if (g == 0) {
        float4 s = sp[0][l];
#pragma unroll
        for (int q = 1; q < 8; q++) {
            float4 v = sp[q][l];
            s.x += v.x; s.y += v.y; s.z += v.z; s.w += v.w;
        }
        float4 bv = ((const float4*)b)[l];
        s.x = fmaxf(s.x + bv.x, 0.f);
        s.y = fmaxf(s.y + bv.y, 0.f);
        s.z = fmaxf(s.z + bv.z, 0.f);
        s.w = fmaxf(s.w + bv.w, 0.f);
        ((float4*)(out + i * OUTD))[l] = s;
    }
}

// =============================================================================
extern "C" void kernel_launch(void* const* d_in, const int* in_sizes, int n_in,
                              void* d_out, int out_size) {
    const float* hidden = (const float*)d_in[0];
    const float* obs2   = (const float*)d_in[2];
    const float* W      = (const float*)d_in[3];
    const float* b      = (const float*)d_in[4];
    float*       out    = (float*)d_out;

    cudaFuncSetAttribute(gemm_mma_kernel, cudaFuncAttributeMaxDynamicSharedMemorySize, SMEM_DYN);

    convW_kernel<<<KDIM * HID / 256, 256>>>(W);
    convH_kernel<<<N_AG * HID / 256, 256>>>(hidden);
    scatter_kernel<<<N_AG / 8, 256>>>(obs2);
    dim3 ggrid(N_AG / 128, KDIM / 128);   // (8, 16)
    gemm_mma_kernel<<<ggrid, 256, SMEM_DYN>>>();
    out_kernel<<<N_AG, 256>>>(b, out);
}

// round 5
// speedup vs baseline: 1.9057x; 1.0731x over previous
#include <cuda_runtime.h>
#include <cuda_bf16.h>
#include <cstdint>

#define N_AG  1024
#define HID   128
#define KDIM  2048
#define OUTD  128
#define CELLS 1024

// ---- scratch (device globals; no allocs allowed) ----
__device__ __nv_bfloat16 g_Ah[N_AG * HID];     // hidden hi
__device__ __nv_bfloat16 g_Al[N_AG * HID];     // hidden lo
__device__ __nv_bfloat16 g_Bh[KDIM * HID];     // Wperm hi
__device__ __nv_bfloat16 g_Bl[KDIM * HID];     // Wperm lo
__device__ float g_P[N_AG * KDIM];             // 8 MB projections
__device__ int   g_ent[N_AG * CELLS];
__device__ int   g_cnt[N_AG];

__device__ __forceinline__ uint32_t smem_u32(const void* p) {
    uint32_t a;
    asm("{ .reg .u64 t; cvta.to.shared.u64 t, %1; cvt.u32.u64 %0, t; }" : "=r"(a) : "l"(p));
    return a;
}
__device__ __forceinline__ void ldsm_x4(uint32_t& r0, uint32_t& r1, uint32_t& r2, uint32_t& r3,
                                        uint32_t addr) {
    asm volatile("ldmatrix.sync.aligned.m8n8.x4.shared.b16 {%0,%1,%2,%3}, [%4];"
                 : "=r"(r0), "=r"(r1), "=r"(r2), "=r"(r3) : "r"(addr));
}
__device__ __forceinline__ void mma16816(float* c, const uint32_t* a, const uint32_t* b) {
    asm volatile("mma.sync.aligned.m16n8k16.row.col.f32.bf16.bf16.f32 "
                 "{%0,%1,%2,%3}, {%4,%5,%6,%7}, {%8,%9}, {%0,%1,%2,%3};"
                 : "+f"(c[0]), "+f"(c[1]), "+f"(c[2]), "+f"(c[3])
                 : "r"(a[0]), "r"(a[1]), "r"(a[2]), "r"(a[3]), "r"(b[0]), "r"(b[1]));
}
__device__ __forceinline__ void cp_async16(uint32_t dst, const void* src) {
    asm volatile("cp.async.cg.shared.global [%0], [%1], 16;" :: "r"(dst), "l"(src) : "memory");
}

// ======================= fused prep kernel ===================================
// blocks [0,1024): convW | [1024,1536): convH | [1536,1664): scatter (8 egos ea)
__global__ void prep_kernel(const float* __restrict__ W,
                            const float* __restrict__ Hs,
                            const float* __restrict__ obs2) {
    const int b0 = blockIdx.x;
    const int t  = threadIdx.x;   // 256

    if (b0 < 1024) {              // ---- convW: permute + bf16 split ----
        int idx = b0 * 256 + t;   // 262144
        float v = W[idx];
        int n = idx >> 11, k = idx & 2047;
        int h = k >> 4, blk = k & 15;
        int row = (blk << 7) | n;
        __nv_bfloat16 hi = __float2bfloat16(v);
        g_Bh[row * HID + h] = hi;
        g_Bl[row * HID + h] = __float2bfloat16(v - __bfloat162float(hi));
        return;
    }
    if (b0 < 1536) {              // ---- convH: bf16 split ----
        int idx = (b0 - 1024) * 256 + t;   // 131072
        float v = Hs[idx];
        __nv_bfloat16 hi = __float2bfloat16(v);
        g_Ah[idx] = hi;
        g_Al[idx] = __float2bfloat16(v - __bfloat162float(hi));
        return;
    }

    // ---- scatter: 8 egos per CTA, set-semantics (max j wins) ----
    __shared__ float2 s_obs[N_AG];
    __shared__ int    w[8][CELLS];
    __shared__ int    cnt[8];
    const int i0 = (b0 - 1536) * 8;

    for (int j = t; j < N_AG; j += 256) s_obs[j] = ((const float2*)obs2)[j];
    for (int c = t; c < 8 * CELLS; c += 256) (&w[0][0])[c] = -1;
    if (t < 8) cnt[t] = 0;
    __syncthreads();

#pragma unroll
    for (int e = 0; e < 8; e++) {
        const int i = i0 + e;
        const float xi = s_obs[i].x, yi = s_obs[i].y;
        if (xi != xi) continue;                      // ego NaN
        for (int j = t; j < N_AG; j += 256) {
            if (j == i) continue;
            float xj = s_obs[j].x, yj = s_obs[j].y;
            if (xj != xj) continue;
            float ox = (xj - xi) * 4.0f + 16.0f;     // exact pow2 scale
            float oy = (yj - yi) * 4.0f + 16.0f;
            if (ox >= 0.0f && ox < 32.0f && oy >= 0.0f && oy < 32.0f)
                atomicMax(&w[e][((int)ox) * 32 + (int)oy], j);
        }
    }
    __syncthreads();

#pragma unroll
    for (int e = 0; e < 8; e++) {
        const int i = i0 + e;
        int* ent = g_ent + (i << 10);
        for (int c = t; c < CELLS; c += 256) {
            int j = w[e][c];
            if (j >= 0) {
                int blk = ((c >> 8) << 2) | ((c & 31) >> 3);
                int p = atomicAdd(&cnt[e], 1);
                ent[p] = (j << 11) | (blk << 7);     // offset into P
            }
        }
    }
    __syncthreads();
    if (t < 8) g_cnt[i0 + t] = cnt[t];
}

// ============================ mma.sync GEMM ==================================
// P = hidden(1024x128) @ Wperm^T(2048x128). grid(8,16), 256 thr, 128x128 tile.
// 3 bf16 passes (Ah*Bh + Ah*Bl + Al*Bh), fragments loaded ONCE per k-step.
#define LDS   136
#define TILE  (128 * LDS)
#define SMEM_DYN (4 * TILE * 2)            // 139264 B

__device__ __forceinline__ void load_tile_async(__nv_bfloat16* dst,
                                                const __nv_bfloat16* src, int row0) {
    const int t = threadIdx.x;             // 256
#pragma unroll
    for (int q = t; q < 2048; q += 256) {  // 16B chunks
        int r = q >> 4, c = q & 15;
        cp_async16(smem_u32(dst + r * LDS + c * 8), src + (row0 + r) * HID + c * 8);
    }
}

__global__ void __launch_bounds__(256, 1) gemm_mma_kernel() {
    extern __shared__ __nv_bfloat16 sm[];
    __nv_bfloat16* sAh = sm;
    __nv_bfloat16* sAl = sm + TILE;
    __nv_bfloat16* sBh = sm + 2 * TILE;
    __nv_bfloat16* sBl = sm + 3 * TILE;

    const int t  = threadIdx.x;
    const int w  = t >> 5;
    const int l  = t & 31;
    const int m0 = blockIdx.x << 7;
    const int n0 = blockIdx.y << 7;
    const int wm = (w >> 2) * 64;
    const int wn = (w & 3) * 32;

    load_tile_async(sAh, g_Ah, m0);
    load_tile_async(sAl, g_Al, m0);
    load_tile_async(sBh, g_Bh, n0);
    load_tile_async(sBl, g_Bl, n0);
    asm volatile("cp.async.commit_group;" ::: "memory");
    asm volatile("cp.async.wait_group 0;" ::: "memory");
    __syncthreads();

    float acc[4][4][4];
#pragma unroll
    for (int mi = 0; mi < 4; mi++)
#pragma unroll
        for (int ni = 0; ni < 4; ni++)
#pragma unroll
            for (int q = 0; q < 4; q++) acc[mi][ni][q] = 0.0f;

    const int aRow = wm + (l & 15);
    const int aCol = (l >> 4) * 8;
    const int bRow = wn + ((l >> 4) * 8) + (l & 7);
    const int bCol = ((l >> 3) & 1) * 8;

    const uint32_t aHB = smem_u32(sAh + aRow * LDS + aCol);
    const uint32_t aLB = smem_u32(sAl + aRow * LDS + aCol);
    const uint32_t bHB = smem_u32(sBh + bRow * LDS + bCol);
    const uint32_t bLB = smem_u32(sBl + bRow * LDS + bCol);

#pragma unroll
    for (int kk = 0; kk < 8; kk++) {
        const uint32_t ko = kk * 32;       // kk*16 elements * 2B
        uint32_t aH[4][4], aL[4][4], bH[4][2], bL[4][2];
#pragma unroll
        for (int mi = 0; mi < 4; mi++) {
            ldsm_x4(aH[mi][0], aH[mi][1], aH[mi][2], aH[mi][3],
                    aHB + mi * (16 * LDS * 2) + ko);
            ldsm_x4(aL[mi][0], aL[mi][1], aL[mi][2], aL[mi][3],
                    aLB + mi * (16 * LDS * 2) + ko);
        }
#pragma unroll
        for (int bi = 0; bi < 2; bi++) {
            ldsm_x4(bH[2 * bi][0], bH[2 * bi][1], bH[2 * bi + 1][0], bH[2 * bi + 1][1],
                    bHB + bi * (16 * LDS * 2) + ko);
            ldsm_x4(bL[2 * bi][0], bL[2 * bi][1], bL[2 * bi + 1][0], bL[2 * bi + 1][1],
                    bLB + bi * (16 * LDS * 2) + ko);
        }
#pragma unroll
        for (int mi = 0; mi < 4; mi++)
#pragma unroll
            for (int ni = 0; ni < 4; ni++) {
                mma16816(acc[mi][ni], aH[mi], bH[ni]);
                mma16816(acc[mi][ni], aH[mi], bL[ni]);
                mma16816(acc[mi][ni], aL[mi], bH[ni]);
            }
    }

    const int g2 = l >> 2, tig = l & 3;
#pragma unroll
    for (int mi = 0; mi < 4; mi++) {
        const int row = m0 + wm + mi * 16 + g2;
#pragma unroll
        for (int ni = 0; ni < 4; ni++) {
            const int col = n0 + wn + ni * 8 + tig * 2;
            *(float2*)(g_P + row * KDIM + col)       = make_float2(acc[mi][ni][0], acc[mi][ni][1]);
            *(float2*)(g_P + (row + 8) * KDIM + col) = make_float2(acc[mi][ni][2], acc[mi][ni][3]);
        }
    }
}

// ============================ output gather =================================
__global__ void out_kernel(const float* __restrict__ b, float* __restrict__ out) {
    __shared__ int    se[CELLS];
    __shared__ float4 sp[8][32];
    const int i = blockIdx.x;
    const int t = threadIdx.x;     // 256
    const int g = t >> 5, l = t & 31;

    const int cnt = g_cnt[i];
    const int* ent = g_ent + (i << 10);
    for (int e = t; e < cnt; e += 256) se[e] = ent[e];
    __syncthreads();

    float4 acc = make_float4(0.f, 0.f, 0.f, 0.f);
    for (int e = g; e < cnt; e += 8) {
        float4 v = *(const float4*)(g_P + se[e] + l * 4);
        acc.x += v.x; acc.y += v.y; acc.z += v.z; acc.w += v.w;
    }
    sp[g][l] = acc;
    __syncthreads();

    if (g == 0) {
        float4 s = sp[0][l];
#pragma unroll
        for (int q = 1; q < 8; q++) {
            float4 v = sp[q][l];
            s.x += v.x; s.y += v.y; s.z += v.z; s.w += v.w;
        }
        float4 bv = ((const float4*)b)[l];
        s.x = fmaxf(s.x + bv.x, 0.f);
        s.y = fmaxf(s.y + bv.y, 0.f);
        s.z = fmaxf(s.z + bv.z, 0.f);
        s.w = fmaxf(s.w + bv.w, 0.f);
        ((float4*)(out + i * OUTD))[l] = s;
    }
}

// =============================================================================
extern "C" void kernel_launch(void* const* d_in, const int* in_sizes, int n_in,
                              void* d_out, int out_size) {
    const float* hidden = (const float*)d_in[0];
    const float* obs2   = (const float*)d_in[2];
    const float* W      = (const float*)d_in[3];
    const float* b      = (const float*)d_in[4];
    float*       out    = (float*)d_out;

    cudaFuncSetAttribute(gemm_mma_kernel, cudaFuncAttributeMaxDynamicSharedMemorySize, SMEM_DYN);

    prep_kernel<<<1664, 256>>>(W, hidden, obs2);
    dim3 ggrid(N_AG / 128, KDIM / 128);   // (8, 16)
    gemm_mma_kernel<<<ggrid, 256, SMEM_DYN>>>();
    out_kernel<<<N_AG, 256>>>(b, out);
}

// round 8
// speedup vs baseline: 2.2507x; 1.1811x over previous
#include <cuda_runtime.h>
#include <cuda_bf16.h>
#include <cstdint>

#define N_AG  1024
#define HID   128
#define KDIM  2048
#define OUTD  128
#define CELLS 1024

// ---- scratch (device globals; no allocs allowed) ----
__device__ __align__(16) __nv_bfloat16 g_Ah[N_AG * HID];     // hidden hi
__device__ __align__(16) __nv_bfloat16 g_Al[N_AG * HID];     // hidden lo
__device__ __align__(16) __nv_bfloat16 g_Bh[KDIM * HID];     // Wperm hi
__device__ __align__(16) __nv_bfloat16 g_Bl[KDIM * HID];     // Wperm lo
__device__ float g_P[N_AG * KDIM];             // 8 MB projections
__device__ int   g_ent[N_AG * CELLS];
__device__ int   g_cnt[N_AG];

__device__ __forceinline__ uint32_t smem_u32(const void* p) {
    uint32_t a;
    asm("{ .reg .u64 t; cvta.to.shared.u64 t, %1; cvt.u32.u64 %0, t; }" : "=r"(a) : "l"(p));
    return a;
}
__device__ __forceinline__ void ldsm_x4(uint32_t& r0, uint32_t& r1, uint32_t& r2, uint32_t& r3,
                                        uint32_t addr) {
    asm volatile("ldmatrix.sync.aligned.m8n8.x4.shared.b16 {%0,%1,%2,%3}, [%4];"
                 : "=r"(r0), "=r"(r1), "=r"(r2), "=r"(r3) : "r"(addr));
}
__device__ __forceinline__ void mma16816(float* c, const uint32_t* a, const uint32_t* b) {
    asm volatile("mma.sync.aligned.m16n8k16.row.col.f32.bf16.bf16.f32 "
                 "{%0,%1,%2,%3}, {%4,%5,%6,%7}, {%8,%9}, {%0,%1,%2,%3};"
                 : "+f"(c[0]), "+f"(c[1]), "+f"(c[2]), "+f"(c[3])
                 : "r"(a[0]), "r"(a[1]), "r"(a[2]), "r"(a[3]), "r"(b[0]), "r"(b[1]));
}
__device__ __forceinline__ void cp_async16(uint32_t dst, const void* src) {
    asm volatile("cp.async.cg.shared.global [%0], [%1], 16;" :: "r"(dst), "l"(src) : "memory");
}

// ======================= fused prep kernel ===================================
// blocks [0,32): convW tiled transpose | [32,160): convH | [160,416): scatter
#define NT 32      // n rows per convW tile
#define KT 256     // k cols per convW tile

struct SmW { float w[NT][KT + 1]; };                           // ~32.1 KB
struct SmS { float2 obs[N_AG]; int w[4][CELLS]; int cnt[4]; }; // ~24.5 KB

__global__ void __launch_bounds__(256) prep_kernel(const float* __restrict__ W,
                                                   const float* __restrict__ Hs,
                                                   const float* __restrict__ obs2) {
    __shared__ union { SmW cw; SmS sc; } sm;
    const int b0 = blockIdx.x;
    const int t  = threadIdx.x;   // 256

    if (b0 < 32) {     // ---- convW: staged transpose, coalesced both ways ----
        const int nt = b0 >> 3, kt = b0 & 7;
        const int n0 = nt * NT, k0 = kt * KT, h0 = kt * 16;
        // load 32x256 fp32 tile: float4 LDG, scalar STS (row stride 257 floats
        // is conflict-free on readout but NOT 16B-aligned -> no STS.128!)
#pragma unroll
        for (int q = t; q < NT * KT / 4; q += 256) {   // 2048 float4s
            int r = q >> 6, c4 = q & 63;
            float4 v = *(const float4*)(W + (n0 + r) * KDIM + k0 + c4 * 4);
            sm.cw.w[r][c4 * 4 + 0] = v.x;
            sm.cw.w[r][c4 * 4 + 1] = v.y;
            sm.cw.w[r][c4 * 4 + 2] = v.z;
            sm.cw.w[r][c4 * 4 + 3] = v.w;
        }
        __syncthreads();
        // write: 512 (blk,nn) rows, 2 per thread; 16 h values each (32B runs)
#pragma unroll
        for (int p = t; p < 512; p += 256) {
            const int blk = p >> 5, nn = p & 31;
            const int r = (blk << 7) | (n0 + nn);
            __align__(16) __nv_bfloat16 hi[16];
            __align__(16) __nv_bfloat16 lo[16];
#pragma unroll
            for (int hr = 0; hr < 16; hr++) {
                float v = sm.cw.w[nn][hr * 16 + blk];
                hi[hr] = __float2bfloat16(v);
                lo[hr] = __float2bfloat16(v - __bfloat162float(hi[hr]));
            }
            *(uint4*)(g_Bh + r * HID + h0)     = *(const uint4*)&hi[0];
            *(uint4*)(g_Bh + r * HID + h0 + 8) = *(const uint4*)&hi[8];
            *(uint4*)(g_Bl + r * HID + h0)     = *(const uint4*)&lo[0];
            *(uint4*)(g_Bl + r * HID + h0 + 8) = *(const uint4*)&lo[8];
        }
        return;
    }
    if (b0 < 160) {    // ---- convH: float4 vectorized bf16 split ----
        int q = (b0 - 32) * 256 + t;                  // 32768 float4s
        float4 v = ((const float4*)Hs)[q];
        __align__(8) __nv_bfloat16 hi[4];
        __align__(8) __nv_bfloat16 lo[4];
        hi[0] = __float2bfloat16(v.x); lo[0] = __float2bfloat16(v.x - __bfloat162float(hi[0]));
        hi[1] = __float2bfloat16(v.y); lo[1] = __float2bfloat16(v.y - __bfloat162float(hi[1]));
        hi[2] = __float2bfloat16(v.z); lo[2] = __float2bfloat16(v.z - __bfloat162float(hi[2]));
        hi[3] = __float2bfloat16(v.w); lo[3] = __float2bfloat16(v.w - __bfloat162float(hi[3]));
        *(uint2*)(g_Ah + q * 4) = *(const uint2*)&hi[0];
        *(uint2*)(g_Al + q * 4) = *(const uint2*)&lo[0];
        return;
    }

    // ---- scatter: 4 egos per CTA, set-semantics (max j wins) ----
    const int i0 = (b0 - 160) * 4;
    for (int j = t; j < N_AG; j += 256) sm.sc.obs[j] = ((const float2*)obs2)[j];
    for (int c = t; c < 4 * CELLS; c += 256) (&sm.sc.w[0][0])[c] = -1;
    if (t < 4) sm.sc.cnt[t] = 0;
    __syncthreads();

#pragma unroll
    for (int e = 0; e < 4; e++) {
        const int i = i0 + e;
        const float xi = sm.sc.obs[i].x, yi = sm.sc.obs[i].y;
        if (xi != xi) continue;                      // ego NaN
        for (int j = t; j < N_AG; j += 256) {
            if (j == i) continue;
            float xj = sm.sc.obs[j].x, yj = sm.sc.obs[j].y;
            if (xj != xj) continue;
            float ox = (xj - xi) * 4.0f + 16.0f;     // exact pow2 scale
            float oy = (yj - yi) * 4.0f + 16.0f;
            if (ox >= 0.0f && ox < 32.0f && oy >= 0.0f && oy < 32.0f)
                atomicMax(&sm.sc.w[e][((int)ox) * 32 + (int)oy], j);
        }
    }
    __syncthreads();

#pragma unroll
    for (int e = 0; e < 4; e++) {
        const int i = i0 + e;
        int* ent = g_ent + (i << 10);
        for (int c = t; c < CELLS; c += 256) {
            int j = sm.sc.w[e][c];
            if (j >= 0) {
                int blk = ((c >> 8) << 2) | ((c & 31) >> 3);
                int p = atomicAdd(&sm.sc.cnt[e], 1);
                ent[p] = (j << 11) | (blk << 7);     // offset into P
            }
        }
    }
    __syncthreads();
    if (t < 4) g_cnt[i0 + t] = sm.sc.cnt[t];
}

// ============================ mma.sync GEMM ==================================
// P = hidden(1024x128) @ Wperm^T(2048x128). grid(8,16), 256 thr, 128x128 tile.
// 3 bf16 passes (Ah*Bh + Ah*Bl + Al*Bh), fragments loaded ONCE per k-step.
#define LDS   136
#define TILE  (128 * LDS)
#define SMEM_DYN (4 * TILE * 2)            // 139264 B

__device__ __forceinline__ void load_tile_async(__nv_bfloat16* dst,
                                                const __nv_bfloat16* src, int row0) {
    const int t = threadIdx.x;             // 256
#pragma unroll
    for (int q = t; q < 2048; q += 256) {  // 16B chunks
        int r = q >> 4, c = q & 15;
        cp_async16(smem_u32(dst + r * LDS + c * 8), src + (row0 + r) * HID + c * 8);
    }
}

__global__ void __launch_bounds__(256, 1) gemm_mma_kernel() {
    extern __shared__ __nv_bfloat16 sm[];
    __nv_bfloat16* sAh = sm;
    __nv_bfloat16* sAl = sm + TILE;
    __nv_bfloat16* sBh = sm + 2 * TILE;
    __nv_bfloat16* sBl = sm + 3 * TILE;

    const int t  = threadIdx.x;
    const int w  = t >> 5;
    const int l  = t & 31;
    const int m0 = blockIdx.x << 7;
    const int n0 = blockIdx.y << 7;
    const int wm = (w >> 2) * 64;
    const int wn = (w & 3) * 32;

    load_tile_async(sAh, g_Ah, m0);
    load_tile_async(sAl, g_Al, m0);
    load_tile_async(sBh, g_Bh, n0);
    load_tile_async(sBl, g_Bl, n0);
    asm volatile("cp.async.commit_group;" ::: "memory");
    asm volatile("cp.async.wait_group 0;" ::: "memory");
    __syncthreads();

    float acc[4][4][4];
#pragma unroll
    for (int mi = 0; mi < 4; mi++)
#pragma unroll
        for (int ni = 0; ni < 4; ni++)
#pragma unroll
            for (int q = 0; q < 4; q++) acc[mi][ni][q] = 0.0f;

    const int aRow = wm + (l & 15);
    const int aCol = (l >> 4) * 8;
    const int bRow = wn + ((l >> 4) * 8) + (l & 7);
    const int bCol = ((l >> 3) & 1) * 8;

    const uint32_t aHB = smem_u32(sAh + aRow * LDS + aCol);
    const uint32_t aLB = smem_u32(sAl + aRow * LDS + aCol);
    const uint32_t bHB = smem_u32(sBh + bRow * LDS + bCol);
    const uint32_t bLB = smem_u32(sBl + bRow * LDS + bCol);

#pragma unroll
    for (int kk = 0; kk < 8; kk++) {
        const uint32_t ko = kk * 32;       // kk*16 elements * 2B
        uint32_t aH[4][4], aL[4][4], bH[4][2], bL[4][2];
#pragma unroll
        for (int mi = 0; mi < 4; mi++) {
            ldsm_x4(aH[mi][0], aH[mi][1], aH[mi][2], aH[mi][3],
                    aHB + mi * (16 * LDS * 2) + ko);
            ldsm_x4(aL[mi][0], aL[mi][1], aL[mi][2], aL[mi][3],
                    aLB + mi * (16 * LDS * 2) + ko);
        }
#pragma unroll
        for (int bi = 0; bi < 2; bi++) {
            ldsm_x4(bH[2 * bi][0], bH[2 * bi][1], bH[2 * bi + 1][0], bH[2 * bi + 1][1],
                    bHB + bi * (16 * LDS * 2) + ko);
            ldsm_x4(bL[2 * bi][0], bL[2 * bi][1], bL[2 * bi + 1][0], bL[2 * bi + 1][1],
                    bLB + bi * (16 * LDS * 2) + ko);
        }
#pragma unroll
        for (int mi = 0; mi < 4; mi++)
#pragma unroll
            for (int ni = 0; ni < 4; ni++) {
                mma16816(acc[mi][ni], aH[mi], bH[ni]);
                mma16816(acc[mi][ni], aH[mi], bL[ni]);
                mma16816(acc[mi][ni], aL[mi], bH[ni]);
            }
    }

    const int g2 = l >> 2, tig = l & 3;
#pragma unroll
    for (int mi = 0; mi < 4; mi++) {
        const int row = m0 + wm + mi * 16 + g2;
#pragma unroll
        for (int ni = 0; ni < 4; ni++) {
            const int col = n0 + wn + ni * 8 + tig * 2;
            *(float2*)(g_P + row * KDIM + col)       = make_float2(acc[mi][ni][0], acc[mi][ni][1]);
            *(float2*)(g_P + (row + 8) * KDIM + col) = make_float2(acc[mi][ni][2], acc[mi][ni][3]);
        }
    }
}

// ============================ output gather =================================
__global__ void out_kernel(const float* __restrict__ b, float* __restrict__ out) {
    __shared__ int    se[CELLS];
    __shared__ float4 sp[8][32];
    const int i = blockIdx.x;
    const int t = threadIdx.x;     // 256
    const int g = t >> 5, l = t & 31;

    const int cnt = g_cnt[i];
    const int* ent = g_ent + (i << 10);
    for (int e = t; e < cnt; e += 256) se[e] = ent[e];
    __syncthreads();

    float4 acc = make_float4(0.f, 0.f, 0.f, 0.f);
    for (int e = g; e < cnt; e += 8) {
        float4 v = *(const float4*)(g_P + se[e] + l * 4);
        acc.x += v.x; acc.y += v.y; acc.z += v.z; acc.w += v.w;
    }
    sp[g][l] = acc;
    __syncthreads();

    if (g == 0) {
        float4 s = sp[0][l];
#pragma unroll
        for (int q = 1; q < 8; q++) {
            float4 v = sp[q][l];
            s.x += v.x; s.y += v.y; s.z += v.z; s.w += v.w;
        }
        float4 bv = ((const float4*)b)[l];
        s.x = fmaxf(s.x + bv.x, 0.f);
        s.y = fmaxf(s.y + bv.y, 0.f);
        s.z = fmaxf(s.z + bv.z, 0.f);
        s.w = fmaxf(s.w + bv.w, 0.f);
        ((float4*)(out + i * OUTD))[l] = s;
    }
}

// =============================================================================
extern "C" void kernel_launch(void* const* d_in, const int* in_sizes, int n_in,
                              void* d_out, int out_size) {
    const float* hidden = (const float*)d_in[0];
    const float* obs2   = (const float*)d_in[2];
    const float* W      = (const float*)d_in[3];
    const float* b      = (const float*)d_in[4];
    float*       out    = (float*)d_out;

    cudaFuncSetAttribute(gemm_mma_kernel, cudaFuncAttributeMaxDynamicSharedMemorySize, SMEM_DYN);

    prep_kernel<<<416, 256>>>(W, hidden, obs2);
    dim3 ggrid(N_AG / 128, KDIM / 128);   // (8, 16)
    gemm_mma_kernel<<<ggrid, 256, SMEM_DYN>>>();
    out_kernel<<<N_AG, 256>>>(b, out);
}

// round 9
// speedup vs baseline: 2.7251x; 1.2108x over previous
#include <cuda_runtime.h>
#include <cuda_bf16.h>
#include <cstdint>

#define N_AG  1024
#define HID   128
#define KDIM  2048
#define OUTD  128
#define CELLS 1024

// ---- scratch (device globals; no allocs allowed) ----
__device__ __align__(16) __nv_bfloat16 g_Ah[N_AG * HID];     // hidden hi
__device__ __align__(16) __nv_bfloat16 g_Al[N_AG * HID];     // hidden lo
__device__ __align__(16) __nv_bfloat16 g_Bh[KDIM * HID];     // Wperm hi
__device__ __align__(16) __nv_bfloat16 g_Bl[KDIM * HID];     // Wperm lo
__device__ float g_P[N_AG * KDIM];             // 8 MB projections
__device__ int   g_ent[N_AG * CELLS];
__device__ int   g_cnt[N_AG];

__device__ __forceinline__ uint32_t smem_u32(const void* p) {
    uint32_t a;
    asm("{ .reg .u64 t; cvta.to.shared.u64 t, %1; cvt.u32.u64 %0, t; }" : "=r"(a) : "l"(p));
    return a;
}
__device__ __forceinline__ void ldsm_x4(uint32_t& r0, uint32_t& r1, uint32_t& r2, uint32_t& r3,
                                        uint32_t addr) {
    asm volatile("ldmatrix.sync.aligned.m8n8.x4.shared.b16 {%0,%1,%2,%3}, [%4];"
                 : "=r"(r0), "=r"(r1), "=r"(r2), "=r"(r3) : "r"(addr));
}
__device__ __forceinline__ void mma16816(float* c, const uint32_t* a, const uint32_t* b) {
    asm volatile("mma.sync.aligned.m16n8k16.row.col.f32.bf16.bf16.f32 "
                 "{%0,%1,%2,%3}, {%4,%5,%6,%7}, {%8,%9}, {%0,%1,%2,%3};"
                 : "+f"(c[0]), "+f"(c[1]), "+f"(c[2]), "+f"(c[3])
                 : "r"(a[0]), "r"(a[1]), "r"(a[2]), "r"(a[3]), "r"(b[0]), "r"(b[1]));
}
__device__ __forceinline__ void cp_async16(uint32_t dst, const void* src) {
    asm volatile("cp.async.cg.shared.global [%0], [%1], 16;" :: "r"(dst), "l"(src) : "memory");
}

// ======================= fused prep kernel ===================================
// blocks [0,64): convW tiled transpose | [64,192): convH | [192,1216): scatter
#define NT 16      // n rows per convW tile
#define KT 256     // k cols per convW tile

struct SmW { float w[NT][KT + 1]; };                        // ~16.1 KB
struct SmS { float2 obs[N_AG]; int w[CELLS]; int cnt; };    // ~12 KB

__global__ void __launch_bounds__(256) prep_kernel(const float* __restrict__ W,
                                                   const float* __restrict__ Hs,
                                                   const float* __restrict__ obs2) {
    __shared__ union { SmW cw; SmS sc; } sm;
    const int b0 = blockIdx.x;
    const int t  = threadIdx.x;   // 256

    if (b0 < 64) {     // ---- convW: staged transpose, coalesced both ways ----
        const int nt = b0 >> 3, kt = b0 & 7;
        const int n0 = nt * NT, k0 = kt * KT, h0 = kt * 16;
        // load 16x256 fp32 tile: float4 LDG, scalar STS (257-stride rows are
        // conflict-free on readout but not 16B aligned -> no STS.128)
#pragma unroll
        for (int q = t; q < NT * KT / 4; q += 256) {   // 1024 float4s
            int r = q >> 6, c4 = q & 63;
            float4 v = *(const float4*)(W + (n0 + r) * KDIM + k0 + c4 * 4);
            sm.cw.w[r][c4 * 4 + 0] = v.x;
            sm.cw.w[r][c4 * 4 + 1] = v.y;
            sm.cw.w[r][c4 * 4 + 2] = v.z;
            sm.cw.w[r][c4 * 4 + 3] = v.w;
        }
        __syncthreads();
        // write: 256 (blk,nn) rows, 1 per thread; 16 h values each (32B runs)
        {
            const int blk = t >> 4, nn = t & 15;
            const int r = (blk << 7) | (n0 + nn);
            __align__(16) __nv_bfloat16 hi[16];
            __align__(16) __nv_bfloat16 lo[16];
#pragma unroll
            for (int hr = 0; hr < 16; hr++) {
                float v = sm.cw.w[nn][hr * 16 + blk];
                hi[hr] = __float2bfloat16(v);
                lo[hr] = __float2bfloat16(v - __bfloat162float(hi[hr]));
            }
            *(uint4*)(g_Bh + r * HID + h0)     = *(const uint4*)&hi[0];
            *(uint4*)(g_Bh + r * HID + h0 + 8) = *(const uint4*)&hi[8];
            *(uint4*)(g_Bl + r * HID + h0)     = *(const uint4*)&lo[0];
            *(uint4*)(g_Bl + r * HID + h0 + 8) = *(const uint4*)&lo[8];
        }
        return;
    }
    if (b0 < 192) {    // ---- convH: float4 vectorized bf16 split ----
        int q = (b0 - 64) * 256 + t;                  // 32768 float4s
        float4 v = ((const float4*)Hs)[q];
        __align__(8) __nv_bfloat16 hi[4];
        __align__(8) __nv_bfloat16 lo[4];
        hi[0] = __float2bfloat16(v.x); lo[0] = __float2bfloat16(v.x - __bfloat162float(hi[0]));
        hi[1] = __float2bfloat16(v.y); lo[1] = __float2bfloat16(v.y - __bfloat162float(hi[1]));
        hi[2] = __float2bfloat16(v.z); lo[2] = __float2bfloat16(v.z - __bfloat162float(hi[2]));
        hi[3] = __float2bfloat16(v.w); lo[3] = __float2bfloat16(v.w - __bfloat162float(hi[3]));
        *(uint2*)(g_Ah + q * 4) = *(const uint2*)&hi[0];
        *(uint2*)(g_Al + q * 4) = *(const uint2*)&lo[0];
        return;
    }

    // ---- scatter: 1 ego per CTA, set-semantics (max j wins) ----
    const int i = b0 - 192;
    for (int j = t; j < N_AG; j += 256) sm.sc.obs[j] = ((const float2*)obs2)[j];
    for (int c = t; c < CELLS; c += 256) sm.sc.w[c] = -1;
    if (t == 0) sm.sc.cnt = 0;
    __syncthreads();

    const float xi = sm.sc.obs[i].x, yi = sm.sc.obs[i].y;
    if (xi != xi) {                                  // ego NaN
        if (t == 0) g_cnt[i] = 0;
        return;
    }
    for (int j = t; j < N_AG; j += 256) {
        if (j == i) continue;
        float xj = sm.sc.obs[j].x, yj = sm.sc.obs[j].y;
        if (xj != xj) continue;
        float ox = (xj - xi) * 4.0f + 16.0f;         // exact pow2 scale
        float oy = (yj - yi) * 4.0f + 16.0f;
        if (ox >= 0.0f && ox < 32.0f && oy >= 0.0f && oy < 32.0f)
            atomicMax(&sm.sc.w[((int)ox) * 32 + (int)oy], j);
    }
    __syncthreads();

    int* ent = g_ent + (i << 10);
    for (int c = t; c < CELLS; c += 256) {
        int j = sm.sc.w[c];
        if (j >= 0) {
            int blk = ((c >> 8) << 2) | ((c & 31) >> 3);
            int p = atomicAdd(&sm.sc.cnt, 1);
            ent[p] = (j << 11) | (blk << 7);         // offset into P
        }
    }
    __syncthreads();
    if (t == 0) g_cnt[i] = sm.sc.cnt;
}

// ============================ mma.sync GEMM ==================================
// P = hidden(1024x128) @ Wperm^T(2048x128). grid(8,16), 256 thr, 128x128 tile.
// 3 bf16 passes (Ah*Bh + Ah*Bl + Al*Bh), fragments loaded ONCE per k-step.
#define LDS   136
#define TILE  (128 * LDS)
#define SMEM_DYN (4 * TILE * 2)            // 139264 B

__device__ __forceinline__ void load_tile_async(__nv_bfloat16* dst,
                                                const __nv_bfloat16* src, int row0) {
    const int t = threadIdx.x;             // 256
#pragma unroll
    for (int q = t; q < 2048; q += 256) {  // 16B chunks
        int r = q >> 4, c = q & 15;
        cp_async16(smem_u32(dst + r * LDS + c * 8), src + (row0 + r) * HID + c * 8);
    }
}

__global__ void __launch_bounds__(256, 1) gemm_mma_kernel() {
    extern __shared__ __nv_bfloat16 sm[];
    __nv_bfloat16* sAh = sm;
    __nv_bfloat16* sAl = sm + TILE;
    __nv_bfloat16* sBh = sm + 2 * TILE;
    __nv_bfloat16* sBl = sm + 3 * TILE;

    const int t  = threadIdx.x;
    const int w  = t >> 5;
    const int l  = t & 31;
    const int m0 = blockIdx.x << 7;
    const int n0 = blockIdx.y << 7;
    const int wm = (w >> 2) * 64;
    const int wn = (w & 3) * 32;

    load_tile_async(sAh, g_Ah, m0);
    load_tile_async(sAl, g_Al, m0);
    load_tile_async(sBh, g_Bh, n0);
    load_tile_async(sBl, g_Bl, n0);
    asm volatile("cp.async.commit_group;" ::: "memory");
    asm volatile("cp.async.wait_group 0;" ::: "memory");
    __syncthreads();

    float acc[4][4][4];
#pragma unroll
    for (int mi = 0; mi < 4; mi++)
#pragma unroll
        for (int ni = 0; ni < 4; ni++)
#pragma unroll
            for (int q = 0; q < 4; q++) acc[mi][ni][q] = 0.0f;

    const int aRow = wm + (l & 15);
    const int aCol = (l >> 4) * 8;
    const int bRow = wn + ((l >> 4) * 8) + (l & 7);
    const int bCol = ((l >> 3) & 1) * 8;

    const uint32_t aHB = smem_u32(sAh + aRow * LDS + aCol);
    const uint32_t aLB = smem_u32(sAl + aRow * LDS + aCol);
    const uint32_t bHB = smem_u32(sBh + bRow * LDS + bCol);
    const uint32_t bLB = smem_u32(sBl + bRow * LDS + bCol);

#pragma unroll
    for (int kk = 0; kk < 8; kk++) {
        const uint32_t ko = kk * 32;       // kk*16 elements * 2B
        uint32_t aH[4][4], aL[4][4], bH[4][2], bL[4][2];
#pragma unroll
        for (int mi = 0; mi < 4; mi++) {
            ldsm_x4(aH[mi][0], aH[mi][1], aH[mi][2], aH[mi][3],
                    aHB + mi * (16 * LDS * 2) + ko);
            ldsm_x4(aL[mi][0], aL[mi][1], aL[mi][2], aL[mi][3],
                    aLB + mi * (16 * LDS * 2) + ko);
        }
#pragma unroll
        for (int bi = 0; bi < 2; bi++) {
            ldsm_x4(bH[2 * bi][0], bH[2 * bi][1], bH[2 * bi + 1][0], bH[2 * bi + 1][1],
                    bHB + bi * (16 * LDS * 2) + ko);
            ldsm_x4(bL[2 * bi][0], bL[2 * bi][1], bL[2 * bi + 1][0], bL[2 * bi + 1][1],
                    bLB + bi * (16 * LDS * 2) + ko);
        }
#pragma unroll
        for (int mi = 0; mi < 4; mi++)
#pragma unroll
            for (int ni = 0; ni < 4; ni++) {
                mma16816(acc[mi][ni], aH[mi], bH[ni]);
                mma16816(acc[mi][ni], aH[mi], bL[ni]);
                mma16816(acc[mi][ni], aL[mi], bH[ni]);
            }
    }

    const int g2 = l >> 2, tig = l & 3;
#pragma unroll
    for (int mi = 0; mi < 4; mi++) {
        const int row = m0 + wm + mi * 16 + g2;
#pragma unroll
        for (int ni = 0; ni < 4; ni++) {
            const int col = n0 + wn + ni * 8 + tig * 2;
            *(float2*)(g_P + row * KDIM + col)       = make_float2(acc[mi][ni][0], acc[mi][ni][1]);
            *(float2*)(g_P + (row + 8) * KDIM + col) = make_float2(acc[mi][ni][2], acc[mi][ni][3]);
        }
    }
}

// ============================ output gather =================================
__global__ void out_kernel(const float* __restrict__ b, float* __restrict__ out) {
    __shared__ int    se[CELLS];
    __shared__ float4 sp[8][32];
    const int i = blockIdx.x;
    const int t = threadIdx.x;     // 256
    const int g = t >> 5, l = t & 31;

    const int cnt = g_cnt[i];
    const int* ent = g_ent + (i << 10);
    for (int e = t; e < cnt; e += 256) se[e] = ent[e];
    __syncthreads();

    float4 acc = make_float4(0.f, 0.f, 0.f, 0.f);
    for (int e = g; e < cnt; e += 8) {
        float4 v = *(const float4*)(g_P + se[e] + l * 4);
        acc.x += v.x; acc.y += v.y; acc.z += v.z; acc.w += v.w;
    }
    sp[g][l] = acc;
    __syncthreads();

    if (g == 0) {
        float4 s = sp[0][l];
#pragma unroll
        for (int q = 1; q < 8; q++) {
            float4 v = sp[q][l];
            s.x += v.x; s.y += v.y; s.z += v.z; s.w += v.w;
        }
        float4 bv = ((const float4*)b)[l];
        s.x = fmaxf(s.x + bv.x, 0.f);
        s.y = fmaxf(s.y + bv.y, 0.f);
        s.z = fmaxf(s.z + bv.z, 0.f);
        s.w = fmaxf(s.w + bv.w, 0.f);
        ((float4*)(out + i * OUTD))[l] = s;
    }
}

// =============================================================================
extern "C" void kernel_launch(void* const* d_in, const int* in_sizes, int n_in,
                              void* d_out, int out_size) {
    const float* hidden = (const float*)d_in[0];
    const float* obs2   = (const float*)d_in[2];
    const float* W      = (const float*)d_in[3];
    const float* b      = (const float*)d_in[4];
    float*       out    = (float*)d_out;

    cudaFuncSetAttribute(gemm_mma_kernel, cudaFuncAttributeMaxDynamicSharedMemorySize, SMEM_DYN);

    prep_kernel<<<1216, 256>>>(W, hidden, obs2);
    dim3 ggrid(N_AG / 128, KDIM / 128);   // (8, 16)
    gemm_mma_kernel<<<ggrid, 256, SMEM_DYN>>>();
    out_kernel<<<N_AG, 256>>>(b, out);
}